// round 3
// baseline (speedup 1.0000x reference)
#include <cuda_runtime.h>

#define NN 100000
#define F  64
#define NCH ((NN + 15) / 16)

// Scratch (allocation-free: __device__ globals), 16B-aligned for float4 views
__device__ __align__(16) float g_agg[(size_t)NN * F];   // segment sums
__device__ __align__(16) float g_cnt[NN];               // in-degree (computed once)
__device__ __align__(16) float g_t1[(size_t)NN * F];    // sage output
__device__ __align__(16) float g_x2[(size_t)NN * F];    // layer-1 output

__global__ void zero_kernel(int with_cnt) {
    int i = blockIdx.x * blockDim.x + threadIdx.x;
    float4* a4 = reinterpret_cast<float4*>(g_agg);
    if (i < NN * F / 4) a4[i] = make_float4(0.f, 0.f, 0.f, 0.f);
    if (with_cnt && i < NN) g_cnt[i] = 0.f;
}

// 16 threads per edge; each thread owns one float4 (16B) slice of the 64-float row.
// Gather x[src] (coalesced 256B/edge), vector-reduce into agg[dst].
__global__ void edge_kernel(const float4* __restrict__ x4,
                            const int* __restrict__ src,
                            const int* __restrict__ dst,
                            int E, int do_cnt) {
    int t = blockIdx.x * blockDim.x + threadIdx.x;
    int e = t >> 4;
    int sub = t & 15;
    if (e >= E) return;
    int s = __ldg(&src[e]);   // all 16 lanes same addr -> L1 broadcast
    int d = __ldg(&dst[e]);
    if ((unsigned)s >= NN || (unsigned)d >= NN) return;  // dtype-safety guard
    float4 v = __ldg(&x4[(size_t)s * 16 + sub]);
    if (do_cnt && sub == 0) atomicAdd(&g_cnt[d], 1.0f);
    float4* a = reinterpret_cast<float4*>(g_agg) + (size_t)d * 16 + sub;
    asm volatile("red.global.add.v4.f32 [%0], {%1,%2,%3,%4};"
                 :: "l"(a), "f"(v.x), "f"(v.y), "f"(v.z), "f"(v.w) : "memory");
}

// out[node][j] = relu( mean[node] @ Wl + bl + xin[node] @ Wr )
// block = (64 features) x (4 groups); each group register-blocks 4 nodes.
__global__ void sage_kernel(const float* __restrict__ xin,
                            const float* __restrict__ Wl,
                            const float* __restrict__ bl,
                            const float* __restrict__ Wr,
                            float* __restrict__ out) {
    __shared__ float sWl[F * F];
    __shared__ float sWr[F * F];
    __shared__ float sM[4][4][F];
    __shared__ float sH[4][4][F];
    int j = threadIdx.x, g = threadIdx.y;
    int tid = g * 64 + j;
    for (int i = tid; i < F * F; i += 256) { sWl[i] = Wl[i]; sWr[i] = Wr[i]; }
    float blj = bl[j];
    for (int chunk = blockIdx.x; chunk < NCH; chunk += gridDim.x) {
        __syncthreads();
        int base = chunk * 16 + g * 4;
        #pragma unroll
        for (int n = 0; n < 4; n++) {
            int node = base + n;
            if (node < NN) {
                float inv = 1.0f / fmaxf(g_cnt[node], 1.0f);
                sM[g][n][j] = g_agg[node * F + j] * inv;
                sH[g][n][j] = xin[node * F + j];
            }
        }
        __syncthreads();
        float acc[4] = {0.f, 0.f, 0.f, 0.f};
        #pragma unroll 16
        for (int k = 0; k < F; k++) {
            float wl = sWl[k * F + j];
            float wr = sWr[k * F + j];
            #pragma unroll
            for (int n = 0; n < 4; n++)
                acc[n] += sM[g][n][k] * wl + sH[g][n][k] * wr;
        }
        #pragma unroll
        for (int n = 0; n < 4; n++) {
            int node = base + n;
            if (node < NN) out[node * F + j] = fmaxf(acc[n] + blj, 0.f);
        }
    }
}

// out[node][j] = (xin[node] @ W + b)[j], optional relu
template <bool RELU>
__global__ void lin_kernel(const float* __restrict__ xin,
                           const float* __restrict__ W,
                           const float* __restrict__ b,
                           float* __restrict__ out) {
    __shared__ float sW[F * F];
    __shared__ float sX[4][4][F];
    int j = threadIdx.x, g = threadIdx.y;
    int tid = g * 64 + j;
    for (int i = tid; i < F * F; i += 256) sW[i] = W[i];
    float bj = b[j];
    for (int chunk = blockIdx.x; chunk < NCH; chunk += gridDim.x) {
        __syncthreads();
        int base = chunk * 16 + g * 4;
        #pragma unroll
        for (int n = 0; n < 4; n++) {
            int node = base + n;
            if (node < NN) sX[g][n][j] = xin[node * F + j];
        }
        __syncthreads();
        float acc[4] = {0.f, 0.f, 0.f, 0.f};
        #pragma unroll 16
        for (int k = 0; k < F; k++) {
            float w = sW[k * F + j];
            #pragma unroll
            for (int n = 0; n < 4; n++)
                acc[n] += sX[g][n][k] * w;
        }
        #pragma unroll
        for (int n = 0; n < 4; n++) {
            int node = base + n;
            if (node < NN) {
                float v = acc[n] + bj;
                out[node * F + j] = RELU ? fmaxf(v, 0.f) : v;
            }
        }
    }
}

extern "C" void kernel_launch(void* const* d_in, const int* in_sizes, int n_in,
                              void* d_out, int out_size) {
    const float* h   = (const float*)d_in[0];
    const int*   ei  = (const int*)d_in[1];    // JAX demotes int64->int32 (no x64)
    const float* w1l = (const float*)d_in[2];
    const float* b1l = (const float*)d_in[3];
    const float* w1r = (const float*)d_in[4];
    const float* wl1 = (const float*)d_in[5];
    const float* bl1 = (const float*)d_in[6];
    const float* w2l = (const float*)d_in[7];
    const float* b2l = (const float*)d_in[8];
    const float* w2r = (const float*)d_in[9];
    const float* wl2 = (const float*)d_in[10];
    const float* bl2 = (const float*)d_in[11];
    float* out = (float*)d_out;

    int E = in_sizes[1] / 2;
    const int* src = ei;
    const int* dst = ei + E;

    void *p_t1 = nullptr, *p_x2 = nullptr;
    cudaGetSymbolAddress(&p_t1, g_t1);
    cudaGetSymbolAddress(&p_x2, g_x2);
    float* t1 = (float*)p_t1;
    float* x2 = (float*)p_x2;

    int zb = (NN * F / 4 + 255) / 256;
    long long eth = (long long)E * 16;
    int ebl = (int)((eth + 255) / 256);
    dim3 nb(64, 4);
    int ng = 1250;

    // Layer 1
    zero_kernel<<<zb, 256>>>(1);
    edge_kernel<<<ebl, 256>>>((const float4*)h, src, dst, E, 1);
    sage_kernel<<<ng, nb>>>(h, w1l, b1l, w1r, t1);
    lin_kernel<true><<<ng, nb>>>(t1, wl1, bl1, x2);
    // Layer 2 (counts reused)
    zero_kernel<<<zb, 256>>>(0);
    edge_kernel<<<ebl, 256>>>((const float4*)x2, src, dst, E, 0);
    sage_kernel<<<ng, nb>>>(x2, w2l, b2l, w2r, t1);
    lin_kernel<false><<<ng, nb>>>(t1, wl2, bl2, out);
}

// round 4
// speedup vs baseline: 1.3863x; 1.3863x over previous
#include <cuda_runtime.h>

#define NN 100000
#define F  64
#define NCH (NN / 16)            // 6250, exact
#define EMAX 1600000
#define SCAN_BS 512
#define NBLK ((NN + SCAN_BS - 1) / SCAN_BS)   // 196

// Scratch (allocation-free: __device__ globals)
__device__ __align__(16) float g_agg[(size_t)NN * F];   // mean-aggregated features
__device__ __align__(16) float g_x2[(size_t)NN * F];    // layer-1 output
__device__ int g_deg[NN];
__device__ int g_cur[NN];
__device__ int g_rowp[NN + 1];
__device__ int g_bsum[SCAN_BS];
__device__ int g_csr[EMAX];

__global__ void zero_idx_kernel() {
    int i = blockIdx.x * blockDim.x + threadIdx.x;
    if (i < NN) { g_deg[i] = 0; g_cur[i] = 0; }
}

__global__ void hist_kernel(const int* __restrict__ dst, int E) {
    int e = blockIdx.x * blockDim.x + threadIdx.x;
    if (e >= E) return;
    int d = __ldg(&dst[e]);
    if ((unsigned)d < NN) atomicAdd(&g_deg[d], 1);
}

// Deterministic 3-phase exclusive scan of g_deg -> g_rowp
__global__ void scanA_kernel() {
    __shared__ int s[SCAN_BS];
    int tid = threadIdx.x;
    int gid = blockIdx.x * SCAN_BS + tid;
    int v = (gid < NN) ? g_deg[gid] : 0;
    s[tid] = v;
    __syncthreads();
    for (int off = 1; off < SCAN_BS; off <<= 1) {
        int t = (tid >= off) ? s[tid - off] : 0;
        __syncthreads();
        s[tid] += t;
        __syncthreads();
    }
    if (gid < NN) g_rowp[gid] = s[tid] - v;       // exclusive within block
    if (tid == SCAN_BS - 1) g_bsum[blockIdx.x] = s[tid];
}

__global__ void scanB_kernel(int E) {
    __shared__ int s[SCAN_BS];
    int tid = threadIdx.x;
    int v = (tid < NBLK) ? g_bsum[tid] : 0;
    s[tid] = v;
    __syncthreads();
    for (int off = 1; off < SCAN_BS; off <<= 1) {
        int t = (tid >= off) ? s[tid - off] : 0;
        __syncthreads();
        s[tid] += t;
        __syncthreads();
    }
    s[tid] -= v;                                   // exclusive
    __syncthreads();
    if (tid < NBLK) g_bsum[tid] = s[tid];
    if (tid == 0) g_rowp[NN] = E;
}

__global__ void scanC_kernel() {
    int gid = blockIdx.x * SCAN_BS + threadIdx.x;
    if (gid < NN) g_rowp[gid] += g_bsum[blockIdx.x];
}

__global__ void fill_kernel(const int* __restrict__ src,
                            const int* __restrict__ dst, int E) {
    int e = blockIdx.x * blockDim.x + threadIdx.x;
    if (e >= E) return;
    int d = __ldg(&dst[e]);
    int s = __ldg(&src[e]);
    if ((unsigned)d >= NN || (unsigned)s >= NN) return;
    int pos = atomicAdd(&g_cur[d], 1);
    g_csr[g_rowp[d] + pos] = s;
}

// CSR mean aggregation: 16 threads per node, each owns one float4 slice.
// No atomics: pure L2-resident gather + one 256B store per node.
__global__ void agg_kernel(const float4* __restrict__ x4,
                           float4* __restrict__ out4) {
    int t = blockIdx.x * blockDim.x + threadIdx.x;
    int node = t >> 4;
    int sub = t & 15;
    if (node >= NN) return;
    int beg = g_rowp[node];
    int end = g_rowp[node + 1];
    float4 a = make_float4(0.f, 0.f, 0.f, 0.f);
    int i = beg;
    for (; i + 2 <= end; i += 2) {
        int s0 = __ldg(&g_csr[i]);
        int s1 = __ldg(&g_csr[i + 1]);
        float4 v0 = __ldg(&x4[(size_t)s0 * 16 + sub]);
        float4 v1 = __ldg(&x4[(size_t)s1 * 16 + sub]);
        a.x += v0.x + v1.x; a.y += v0.y + v1.y;
        a.z += v0.z + v1.z; a.w += v0.w + v1.w;
    }
    if (i < end) {
        int s0 = __ldg(&g_csr[i]);
        float4 v0 = __ldg(&x4[(size_t)s0 * 16 + sub]);
        a.x += v0.x; a.y += v0.y; a.z += v0.z; a.w += v0.w;
    }
    float inv = 1.0f / (float)max(end - beg, 1);
    out4[(size_t)node * 16 + sub] = make_float4(a.x * inv, a.y * inv, a.z * inv, a.w * inv);
}

// Fused layer: out = act2( relu( mean@Wl + bl + x@Wr ) @ W2 + b2 )
// block (64 features) x (4 groups); each group register-blocks 4 nodes.
// Node-data smem reads are broadcast LDS.128 (float4 over k).
template <bool RELU2>
__global__ void fused_layer(const float* __restrict__ xin,
                            const float* __restrict__ Wl,
                            const float* __restrict__ bl,
                            const float* __restrict__ Wr,
                            const float* __restrict__ W2,
                            const float* __restrict__ b2,
                            float* __restrict__ out) {
    extern __shared__ float sm[];
    float* sWl = sm;             // 4096
    float* sWr = sm + 4096;      // 4096
    float* sW2 = sm + 8192;      // 4096
    float* sM  = sm + 12288;     // 1024 (16 nodes x 64)
    float* sH  = sm + 13312;     // 1024
    float* sT  = sm + 14336;     // 1024
    int j = threadIdx.x, g = threadIdx.y;
    int tid = g * 64 + j;
    for (int i = tid; i < F * F; i += 256) {
        sWl[i] = Wl[i]; sWr[i] = Wr[i]; sW2[i] = W2[i];
    }
    float blj = bl[j];
    float b2j = b2[j];
    for (int chunk = blockIdx.x; chunk < NCH; chunk += gridDim.x) {
        __syncthreads();
        int base = chunk * 16 + g * 4;
        #pragma unroll
        for (int n = 0; n < 4; n++) {
            int node = base + n;
            sM[(g * 4 + n) * F + j] = g_agg[(size_t)node * F + j];
            sH[(g * 4 + n) * F + j] = xin[(size_t)node * F + j];
        }
        __syncthreads();
        // Stage 1: sage
        float acc[4] = {0.f, 0.f, 0.f, 0.f};
        #pragma unroll
        for (int k4 = 0; k4 < F / 4; k4++) {
            float wl0 = sWl[(4 * k4 + 0) * F + j];
            float wl1 = sWl[(4 * k4 + 1) * F + j];
            float wl2 = sWl[(4 * k4 + 2) * F + j];
            float wl3 = sWl[(4 * k4 + 3) * F + j];
            float wr0 = sWr[(4 * k4 + 0) * F + j];
            float wr1 = sWr[(4 * k4 + 1) * F + j];
            float wr2 = sWr[(4 * k4 + 2) * F + j];
            float wr3 = sWr[(4 * k4 + 3) * F + j];
            #pragma unroll
            for (int n = 0; n < 4; n++) {
                float4 mv = *reinterpret_cast<const float4*>(&sM[(g * 4 + n) * F + 4 * k4]);
                float4 hv = *reinterpret_cast<const float4*>(&sH[(g * 4 + n) * F + 4 * k4]);
                acc[n] += mv.x * wl0 + mv.y * wl1 + mv.z * wl2 + mv.w * wl3
                        + hv.x * wr0 + hv.y * wr1 + hv.z * wr2 + hv.w * wr3;
            }
        }
        __syncthreads();
        #pragma unroll
        for (int n = 0; n < 4; n++)
            sT[(g * 4 + n) * F + j] = fmaxf(acc[n] + blj, 0.f);
        __syncthreads();
        // Stage 2: linear
        float a2[4] = {0.f, 0.f, 0.f, 0.f};
        #pragma unroll
        for (int k4 = 0; k4 < F / 4; k4++) {
            float w0 = sW2[(4 * k4 + 0) * F + j];
            float w1 = sW2[(4 * k4 + 1) * F + j];
            float w2 = sW2[(4 * k4 + 2) * F + j];
            float w3 = sW2[(4 * k4 + 3) * F + j];
            #pragma unroll
            for (int n = 0; n < 4; n++) {
                float4 tv = *reinterpret_cast<const float4*>(&sT[(g * 4 + n) * F + 4 * k4]);
                a2[n] += tv.x * w0 + tv.y * w1 + tv.z * w2 + tv.w * w3;
            }
        }
        #pragma unroll
        for (int n = 0; n < 4; n++) {
            int node = base + n;
            float v = a2[n] + b2j;
            out[(size_t)node * F + j] = RELU2 ? fmaxf(v, 0.f) : v;
        }
    }
}

extern "C" void kernel_launch(void* const* d_in, const int* in_sizes, int n_in,
                              void* d_out, int out_size) {
    const float* h   = (const float*)d_in[0];
    const int*   ei  = (const int*)d_in[1];    // JAX demotes int64->int32
    const float* w1l = (const float*)d_in[2];
    const float* b1l = (const float*)d_in[3];
    const float* w1r = (const float*)d_in[4];
    const float* wl1 = (const float*)d_in[5];
    const float* bl1 = (const float*)d_in[6];
    const float* w2l = (const float*)d_in[7];
    const float* b2l = (const float*)d_in[8];
    const float* w2r = (const float*)d_in[9];
    const float* wl2 = (const float*)d_in[10];
    const float* bl2 = (const float*)d_in[11];
    float* out = (float*)d_out;

    int E = in_sizes[1] / 2;
    if (E > EMAX) E = EMAX;
    const int* src = ei;
    const int* dst = ei + E;

    void *p_agg = nullptr, *p_x2 = nullptr;
    cudaGetSymbolAddress(&p_agg, g_agg);
    cudaGetSymbolAddress(&p_x2, g_x2);
    float* agg = (float*)p_agg;
    float* x2  = (float*)p_x2;

    static bool attr_set = false;
    if (!attr_set) {
        cudaFuncSetAttribute(fused_layer<true>,
                             cudaFuncAttributeMaxDynamicSharedMemorySize, 61440);
        cudaFuncSetAttribute(fused_layer<false>,
                             cudaFuncAttributeMaxDynamicSharedMemorySize, 61440);
        attr_set = true;
    }

    int eb = (E + 255) / 256;
    dim3 nb(64, 4);

    // CSR build (per-launch, deterministic row pointers)
    zero_idx_kernel<<<(NN + 255) / 256, 256>>>();
    hist_kernel<<<eb, 256>>>(dst, E);
    scanA_kernel<<<NBLK, SCAN_BS>>>();
    scanB_kernel<<<1, SCAN_BS>>>(E);
    scanC_kernel<<<NBLK, SCAN_BS>>>();
    fill_kernel<<<eb, 256>>>(src, dst, E);

    // Layer 1
    agg_kernel<<<(NN * 16 + 255) / 256, 256>>>((const float4*)h, (float4*)agg);
    fused_layer<true><<<1250, nb, 61440>>>(h, w1l, b1l, w1r, wl1, bl1, x2);
    // Layer 2
    agg_kernel<<<(NN * 16 + 255) / 256, 256>>>((const float4*)x2, (float4*)agg);
    fused_layer<false><<<1250, nb, 61440>>>(x2, w2l, b2l, w2r, wl2, bl2, out);
}